// round 2
// baseline (speedup 1.0000x reference)
#include <cuda_runtime.h>
#include <cstdint>

#define NN 100000
#define NE 1600000
#define FF 128
#define CC 64

// ---------------- scratch (static device globals; no allocation) ----------------
__device__ int   g_cnt[NN];
__device__ int   g_rowptr[NN + 1];
__device__ int   g_cursor[NN];
__device__ int   g_col[NE];
__device__ float g_mean[(size_t)NN * 128];  // layer1 mean(x); reused as PQ for layer2
__device__ float g_h[(size_t)NN * 128];     // hidden activations

// ---------------- CSR build ----------------
__global__ void k_zero_cnt() {
    int i = blockIdx.x * blockDim.x + threadIdx.x;
    if (i < NN) g_cnt[i] = 0;
}

__global__ void k_count(const int* __restrict__ dst) {
    int e = blockIdx.x * blockDim.x + threadIdx.x;
    if (e < NE) atomicAdd(&g_cnt[dst[e]], 1);
}

__global__ void k_scan() {
    __shared__ int sh[1024];
    const int T = 1024;
    int t = threadIdx.x;
    const int chunk = (NN + T - 1) / T;   // 98
    int b = t * chunk;
    int e = min(b + chunk, NN);
    int s = 0;
    for (int i = b; i < e; i++) s += g_cnt[i];
    sh[t] = s;
    __syncthreads();
    for (int off = 1; off < T; off <<= 1) {
        int v = (t >= off) ? sh[t - off] : 0;
        __syncthreads();
        sh[t] += v;
        __syncthreads();
    }
    int run = sh[t] - s;   // exclusive prefix
    for (int i = b; i < e; i++) {
        int c = g_cnt[i];
        g_rowptr[i] = run;
        g_cursor[i] = run;
        run += c;
    }
    if (t == T - 1) g_rowptr[NN] = run;
}

__global__ void k_fill(const int* __restrict__ src, const int* __restrict__ dst) {
    int e = blockIdx.x * blockDim.x + threadIdx.x;
    if (e < NE) {
        int d = dst[e];
        int pos = atomicAdd(&g_cursor[d], 1);
        g_col[pos] = src[e];
    }
}

// ---------------- aggregation: mean of 128-wide rows, one warp per node ----------------
__global__ void k_agg128(const float* __restrict__ X) {
    int node = blockIdx.x * (blockDim.x >> 5) + (threadIdx.x >> 5);
    if (node >= NN) return;
    int lane = threadIdx.x & 31;
    int b = g_rowptr[node], e = g_rowptr[node + 1];
    float4 acc = make_float4(0.f, 0.f, 0.f, 0.f);
    int i = b;
    for (; i + 4 <= e; i += 4) {
        int u0 = g_col[i + 0], u1 = g_col[i + 1], u2 = g_col[i + 2], u3 = g_col[i + 3];
        float4 v0 = *((const float4*)(X + (size_t)u0 * FF) + lane);
        float4 v1 = *((const float4*)(X + (size_t)u1 * FF) + lane);
        float4 v2 = *((const float4*)(X + (size_t)u2 * FF) + lane);
        float4 v3 = *((const float4*)(X + (size_t)u3 * FF) + lane);
        acc.x += (v0.x + v1.x) + (v2.x + v3.x);
        acc.y += (v0.y + v1.y) + (v2.y + v3.y);
        acc.z += (v0.z + v1.z) + (v2.z + v3.z);
        acc.w += (v0.w + v1.w) + (v2.w + v3.w);
    }
    for (; i < e; i++) {
        int u = g_col[i];
        float4 v = *((const float4*)(X + (size_t)u * FF) + lane);
        acc.x += v.x; acc.y += v.y; acc.z += v.z; acc.w += v.w;
    }
    float inv = 1.f / (float)max(e - b, 1);
    float4 r = make_float4(acc.x * inv, acc.y * inv, acc.z * inv, acc.w * inv);
    *((float4*)(g_mean + (size_t)node * FF) + lane) = r;
}

// ---------------- GEMM: C[BMx64] tile += A[mtile,128] @ W[64rows,128]^T ----------------
#define BM 128
#define BN 64
#define BK 32

__device__ __forceinline__ void gemm_accum(
    const float* __restrict__ A,     // [NN x 128] row-major
    const float* __restrict__ W,     // >=64 rows x 128, row-major (pre-offset)
    int mbase, int tid, float (&acc)[8][4],
    float (*As)[BK + 1], float (*Ws)[BN])
{
    for (int kb = 0; kb < 128; kb += BK) {
        // load A tile (128 rows x 32 cols), zero-fill past NN
#pragma unroll
        for (int j = 0; j < 4; j++) {
            int idx = tid + j * 256;
            int r = idx >> 3, c4 = idx & 7;
            int m = mbase + r;
            float4 v = make_float4(0.f, 0.f, 0.f, 0.f);
            if (m < NN) v = *(const float4*)(A + (size_t)m * 128 + kb + c4 * 4);
            float* d = &As[r][c4 * 4];
            d[0] = v.x; d[1] = v.y; d[2] = v.z; d[3] = v.w;
        }
        // load W tile transposed: Ws[k][n] = W[n][kb+k]
        {
            int n = tid >> 2;            // 0..63
            int k0 = (tid & 3) * 8;      // 0,8,16,24
            const float* wp = W + (size_t)n * 128 + kb + k0;
#pragma unroll
            for (int i = 0; i < 8; i++) Ws[k0 + i][n] = wp[i];
        }
        __syncthreads();
        int m0 = (tid >> 4) * 8;
        int n0 = (tid & 15) * 4;
#pragma unroll
        for (int k = 0; k < BK; k++) {
            float4 w = *(const float4*)&Ws[k][n0];
#pragma unroll
            for (int r = 0; r < 8; r++) {
                float a = As[m0 + r][k];
                acc[r][0] += a * w.x;
                acc[r][1] += a * w.y;
                acc[r][2] += a * w.z;
                acc[r][3] += a * w.w;
            }
        }
        __syncthreads();
    }
}

// layer 1: h = relu(mean @ W1l^T + x @ W1r^T + b1l)   (output 128 cols; blockIdx.y = col half)
__global__ void __launch_bounds__(256)
k_gemm1(const float* __restrict__ X,
        const float* __restrict__ W1l, const float* __restrict__ W1r,
        const float* __restrict__ b1l)
{
    __shared__ float As[BM][BK + 1];
    __shared__ float Ws[BK][BN];
    int tid = threadIdx.x;
    int mbase = blockIdx.x * BM;
    int nb = blockIdx.y * BN;
    float acc[8][4];
#pragma unroll
    for (int r = 0; r < 8; r++)
#pragma unroll
        for (int c = 0; c < 4; c++) acc[r][c] = 0.f;

    gemm_accum(g_mean, W1l + (size_t)nb * 128, mbase, tid, acc, As, Ws);
    gemm_accum(X,      W1r + (size_t)nb * 128, mbase, tid, acc, As, Ws);

    int m0 = mbase + (tid >> 4) * 8;
    int n0 = nb + (tid & 15) * 4;
    float4 bias = *(const float4*)(b1l + n0);
#pragma unroll
    for (int r = 0; r < 8; r++) {
        int m = m0 + r;
        if (m < NN) {
            float4 o;
            o.x = fmaxf(acc[r][0] + bias.x, 0.f);
            o.y = fmaxf(acc[r][1] + bias.y, 0.f);
            o.z = fmaxf(acc[r][2] + bias.z, 0.f);
            o.w = fmaxf(acc[r][3] + bias.w, 0.f);
            *(float4*)(g_h + (size_t)m * 128 + n0) = o;
        }
    }
}

// layer 2 projections: PQ[:,0:64] = h @ W2l^T ; PQ[:,64:128] = h @ W2r^T + b2l
__global__ void __launch_bounds__(256)
k_gemm2(const float* __restrict__ W2l, const float* __restrict__ W2r,
        const float* __restrict__ b2l)
{
    __shared__ float As[BM][BK + 1];
    __shared__ float Ws[BK][BN];
    int tid = threadIdx.x;
    int mbase = blockIdx.x * BM;
    int half = blockIdx.y;
    const float* W = half ? W2r : W2l;
    float acc[8][4];
#pragma unroll
    for (int r = 0; r < 8; r++)
#pragma unroll
        for (int c = 0; c < 4; c++) acc[r][c] = 0.f;

    gemm_accum(g_h, W, mbase, tid, acc, As, Ws);

    int m0 = mbase + (tid >> 4) * 8;
    int n0 = (tid & 15) * 4;
    float4 bias = make_float4(0.f, 0.f, 0.f, 0.f);
    if (half) bias = *(const float4*)(b2l + n0);
#pragma unroll
    for (int r = 0; r < 8; r++) {
        int m = m0 + r;
        if (m < NN) {
            float4 o;
            o.x = acc[r][0] + bias.x;
            o.y = acc[r][1] + bias.y;
            o.z = acc[r][2] + bias.z;
            o.w = acc[r][3] + bias.w;
            *(float4*)(g_mean + (size_t)m * 128 + half * 64 + n0) = o;
        }
    }
}

// ---------------- final: out = log_softmax(mean_agg(p) + q), one warp per node ----------------
__global__ void k_final(float* __restrict__ out) {
    int node = blockIdx.x * (blockDim.x >> 5) + (threadIdx.x >> 5);
    if (node >= NN) return;
    int lane = threadIdx.x & 31;
    int b = g_rowptr[node], e = g_rowptr[node + 1];
    float2 acc = make_float2(0.f, 0.f);
    const float* PQ = g_mean;
    int i = b;
    for (; i + 4 <= e; i += 4) {
        int u0 = g_col[i + 0], u1 = g_col[i + 1], u2 = g_col[i + 2], u3 = g_col[i + 3];
        float2 v0 = *((const float2*)(PQ + (size_t)u0 * 128) + lane);
        float2 v1 = *((const float2*)(PQ + (size_t)u1 * 128) + lane);
        float2 v2 = *((const float2*)(PQ + (size_t)u2 * 128) + lane);
        float2 v3 = *((const float2*)(PQ + (size_t)u3 * 128) + lane);
        acc.x += (v0.x + v1.x) + (v2.x + v3.x);
        acc.y += (v0.y + v1.y) + (v2.y + v3.y);
    }
    for (; i < e; i++) {
        int u = g_col[i];
        float2 v = *((const float2*)(PQ + (size_t)u * 128) + lane);
        acc.x += v.x; acc.y += v.y;
    }
    float inv = 1.f / (float)max(e - b, 1);
    float2 q = *((const float2*)(PQ + (size_t)node * 128 + 64) + lane);
    float r0 = acc.x * inv + q.x;
    float r1 = acc.y * inv + q.y;

    // log_softmax over 64 values (2 per lane)
    float mx = fmaxf(r0, r1);
#pragma unroll
    for (int off = 16; off > 0; off >>= 1)
        mx = fmaxf(mx, __shfl_xor_sync(0xffffffffu, mx, off));
    float se = expf(r0 - mx) + expf(r1 - mx);
#pragma unroll
    for (int off = 16; off > 0; off >>= 1)
        se += __shfl_xor_sync(0xffffffffu, se, off);
    float l = logf(se);
    float2 o = make_float2(r0 - mx - l, r1 - mx - l);
    *((float2*)(out + (size_t)node * CC) + lane) = o;
}

// ---------------- launch ----------------
extern "C" void kernel_launch(void* const* d_in, const int* in_sizes, int n_in,
                              void* d_out, int out_size) {
    const float* x   = (const float*)d_in[0];
    const int*   ei  = (const int*)d_in[1];     // [2, NE] int32 (JAX x64 disabled)
    const int*   src = ei;
    const int*   dst = ei + NE;
    const float* W1l = (const float*)d_in[2];
    const float* b1l = (const float*)d_in[3];
    const float* W1r = (const float*)d_in[4];
    const float* W2l = (const float*)d_in[5];
    const float* b2l = (const float*)d_in[6];
    const float* W2r = (const float*)d_in[7];
    float* out = (float*)d_out;

    // CSR build (by destination)
    k_zero_cnt<<<(NN + 255) / 256, 256>>>();
    k_count<<<(NE + 255) / 256, 256>>>(dst);
    k_scan<<<1, 1024>>>();
    k_fill<<<(NE + 255) / 256, 256>>>(src, dst);

    // layer 1
    k_agg128<<<(NN + 7) / 8, 256>>>(x);                       // g_mean = mean(x)
    dim3 g1((NN + BM - 1) / BM, 2);
    k_gemm1<<<g1, 256>>>(x, W1l, W1r, b1l);                   // g_h = relu(...)

    // layer 2 (project before aggregating: mean commutes with linear map)
    dim3 g2((NN + BM - 1) / BM, 2);
    k_gemm2<<<g2, 256>>>(W2l, W2r, b2l);                      // g_mean = [p | q]
    k_final<<<(NN + 7) / 8, 256>>>(out);                      // mean(p)+q, log_softmax
}

// round 4
// speedup vs baseline: 1.2214x; 1.2214x over previous
#include <cuda_runtime.h>
#include <cuda_bf16.h>
#include <cstdint>

#define NN 100000
#define NE 1600000
#define FF 128
#define CC 64

// ======================= scratch (static device globals) =======================
__device__ int   g_cnt[NN];
__device__ int   g_rowptr[NN + 1];
__device__ int   g_cursor[NN];
__device__ int   g_col[NE];
__device__ float g_mean[(size_t)NN * 128];     // PQ output of layer2 (for k_final)
__device__ uint32_t g_mhi[(size_t)NN * 64];    // mean(x) packed bf16x2 hi
__device__ uint32_t g_mlo[(size_t)NN * 64];    // mean(x) packed bf16x2 lo
__device__ uint32_t g_hhi[(size_t)NN * 64];    // h packed bf16x2 hi
__device__ uint32_t g_hlo[(size_t)NN * 64];    // h packed bf16x2 lo
// weights as bf16 hi/lo, row-major [n][k]
__device__ unsigned short g_w1hi[128 * 256];
__device__ unsigned short g_w1lo[128 * 256];
__device__ unsigned short g_w2hi[128 * 128];
__device__ unsigned short g_w2lo[128 * 128];

// ======================= small helpers =======================
__device__ __forceinline__ uint32_t smem_to_u32(const void* p) {
    uint32_t a;
    asm("{ .reg .u64 t; cvta.to.shared.u64 t, %1; cvt.u32.u64 %0, t; }" : "=r"(a) : "l"(p));
    return a;
}

__device__ __forceinline__ void ldm_x4(uint32_t* r, uint32_t addr) {
    asm volatile("ldmatrix.sync.aligned.m8n8.x4.shared.b16 {%0,%1,%2,%3}, [%4];"
                 : "=r"(r[0]), "=r"(r[1]), "=r"(r[2]), "=r"(r[3]) : "r"(addr));
}

__device__ __forceinline__ void mma_bf16(float* d, const uint32_t* a, uint32_t b0, uint32_t b1) {
    asm volatile(
        "mma.sync.aligned.m16n8k16.row.col.f32.bf16.bf16.f32 "
        "{%0,%1,%2,%3}, {%4,%5,%6,%7}, {%8,%9}, {%0,%1,%2,%3};"
        : "+f"(d[0]), "+f"(d[1]), "+f"(d[2]), "+f"(d[3])
        : "r"(a[0]), "r"(a[1]), "r"(a[2]), "r"(a[3]), "r"(b0), "r"(b1));
}

__device__ __forceinline__ void split_pack(float a, float b, uint32_t& hi, uint32_t& lo) {
    __nv_bfloat16 ah = __float2bfloat16(a), bh = __float2bfloat16(b);
    float ar = a - __bfloat162float(ah);
    float br = b - __bfloat162float(bh);
    hi = (uint32_t)__bfloat16_as_ushort(ah) | ((uint32_t)__bfloat16_as_ushort(bh) << 16);
    lo = (uint32_t)__bfloat16_as_ushort(__float2bfloat16(ar))
       | ((uint32_t)__bfloat16_as_ushort(__float2bfloat16(br)) << 16);
}

// ======================= CSR build =======================
__global__ void k_zero_cnt() {
    int i = blockIdx.x * blockDim.x + threadIdx.x;
    if (i < NN) g_cnt[i] = 0;
}

__global__ void k_count(const int* __restrict__ dst) {
    int e = blockIdx.x * blockDim.x + threadIdx.x;
    if (e < NE) atomicAdd(&g_cnt[dst[e]], 1);
}

__global__ void k_scan() {
    __shared__ int sh[1024];
    const int T = 1024;
    int t = threadIdx.x;
    const int chunk = (NN + T - 1) / T;
    int b = t * chunk;
    int e = min(b + chunk, NN);
    int s = 0;
    for (int i = b; i < e; i++) s += g_cnt[i];
    sh[t] = s;
    __syncthreads();
    for (int off = 1; off < T; off <<= 1) {
        int v = (t >= off) ? sh[t - off] : 0;
        __syncthreads();
        sh[t] += v;
        __syncthreads();
    }
    int run = sh[t] - s;
    for (int i = b; i < e; i++) {
        int c = g_cnt[i];
        g_rowptr[i] = run;
        g_cursor[i] = run;
        run += c;
    }
    if (t == T - 1) g_rowptr[NN] = run;
}

__global__ void k_fill(const int* __restrict__ src, const int* __restrict__ dst) {
    int e = blockIdx.x * blockDim.x + threadIdx.x;
    if (e < NE) {
        int d = dst[e];
        int pos = atomicAdd(&g_cursor[d], 1);
        g_col[pos] = src[e];
    }
}

// ======================= aggregation (warp per node) -> bf16 splits =======================
__global__ void k_agg128(const float* __restrict__ X) {
    int node = blockIdx.x * (blockDim.x >> 5) + (threadIdx.x >> 5);
    if (node >= NN) return;
    int lane = threadIdx.x & 31;
    int b = g_rowptr[node], e = g_rowptr[node + 1];
    float4 acc = make_float4(0.f, 0.f, 0.f, 0.f);
    int i = b;
    for (; i + 4 <= e; i += 4) {
        int u0 = g_col[i + 0], u1 = g_col[i + 1], u2 = g_col[i + 2], u3 = g_col[i + 3];
        float4 v0 = *((const float4*)(X + (size_t)u0 * FF) + lane);
        float4 v1 = *((const float4*)(X + (size_t)u1 * FF) + lane);
        float4 v2 = *((const float4*)(X + (size_t)u2 * FF) + lane);
        float4 v3 = *((const float4*)(X + (size_t)u3 * FF) + lane);
        acc.x += (v0.x + v1.x) + (v2.x + v3.x);
        acc.y += (v0.y + v1.y) + (v2.y + v3.y);
        acc.z += (v0.z + v1.z) + (v2.z + v3.z);
        acc.w += (v0.w + v1.w) + (v2.w + v3.w);
    }
    for (; i < e; i++) {
        int u = g_col[i];
        float4 v = *((const float4*)(X + (size_t)u * FF) + lane);
        acc.x += v.x; acc.y += v.y; acc.z += v.z; acc.w += v.w;
    }
    float inv = 1.f / (float)max(e - b, 1);
    uint32_t h0, l0, h1, l1;
    split_pack(acc.x * inv, acc.y * inv, h0, l0);
    split_pack(acc.z * inv, acc.w * inv, h1, l1);
    uint32_t* dh = g_mhi + (size_t)node * 64 + lane * 2;
    uint32_t* dl = g_mlo + (size_t)node * 64 + lane * 2;
    dh[0] = h0; dh[1] = h1;
    dl[0] = l0; dl[1] = l1;
}

// ======================= weight prep: fp32 -> bf16 hi/lo row-major =======================
__global__ void k_prepW(const float* __restrict__ W1l, const float* __restrict__ W1r,
                        const float* __restrict__ W2l, const float* __restrict__ W2r) {
    int idx = blockIdx.x * blockDim.x + threadIdx.x;
    if (idx < 128 * 256) {
        int n = idx >> 8, k = idx & 255;
        float w = (k < 128) ? W1l[n * 128 + k] : W1r[n * 128 + (k - 128)];
        __nv_bfloat16 h = __float2bfloat16(w);
        g_w1hi[idx] = __bfloat16_as_ushort(h);
        g_w1lo[idx] = __bfloat16_as_ushort(__float2bfloat16(w - __bfloat162float(h)));
    } else {
        int i2 = idx - 128 * 256;
        if (i2 < 128 * 128) {
            int n = i2 >> 7, k = i2 & 127;
            float w = (n < 64) ? W2l[n * 128 + k] : W2r[(n - 64) * 128 + k];
            __nv_bfloat16 h = __float2bfloat16(w);
            g_w2hi[i2] = __bfloat16_as_ushort(h);
            g_w2lo[i2] = __bfloat16_as_ushort(__float2bfloat16(w - __bfloat162float(h)));
        }
    }
}

// ======================= HMMA GEMM =======================
// LAYER 1: D[128x128] = [mean|x][128x256] @ W1cat^T  -> h (bias+relu) packed bf16 hi/lo
// LAYER 2: D[128x128] = h[128x128] @ [W2l;W2r]^T     -> PQ fp32 (+b2l on cols 64..127)
// 3-term split: D = Ahi*Bhi + Ahi*Blo + Alo*Bhi
#define ASTR 72   // bf16 elements per A smem row (144B: 16B-aligned, ldmatrix conflict-free)

template <int LAYER>
__global__ void __launch_bounds__(256, 1)
k_mmagemm(const float* __restrict__ X, const float* __restrict__ b1,
          const float* __restrict__ b2)
{
    constexpr int K     = (LAYER == 1) ? 256 : 128;
    constexpr int NCH   = K / 64;            // K chunks of 64
    constexpr int BSTR  = K + 8;             // bf16 per B smem row (pad: conflict-free frag LDS)
    constexpr int AHI   = 0;
    constexpr int ALO   = 128 * ASTR * 2;    // 18432
    constexpr int BHI   = 2 * 128 * ASTR * 2;  // 36864
    constexpr int BSPL  = 128 * BSTR * 2;
    constexpr int BLO   = BHI + BSPL;

    extern __shared__ char smem[];
    const uint32_t smem_base = smem_to_u32(smem);
    const int tid  = threadIdx.x;
    const int warp = tid >> 5;
    const int lane = tid & 31;
    const int wr   = warp >> 2;   // 0..1 : 64-row half
    const int wc   = warp & 3;    // 0..3 : 32-col quarter
    const int mbase = blockIdx.x * 128;

    // ---- copy W (hi/lo) into smem, padded stride ----
    {
        const uint4* shi = (LAYER == 1) ? (const uint4*)g_w1hi : (const uint4*)g_w2hi;
        const uint4* slo = (LAYER == 1) ? (const uint4*)g_w1lo : (const uint4*)g_w2lo;
        const int rowv = K / 8;  // uint4 per source row
        for (int i = tid; i < 128 * rowv; i += 256) {
            int n = i / rowv, c = i - n * rowv;
            *(uint4*)(smem + BHI + n * (BSTR * 2) + c * 16) = shi[i];
            *(uint4*)(smem + BLO + n * (BSTR * 2) + c * 16) = slo[i];
        }
    }

    float acc[4][4][4];
#pragma unroll
    for (int mt = 0; mt < 4; mt++)
#pragma unroll
        for (int nt = 0; nt < 4; nt++)
#pragma unroll
            for (int q = 0; q < 4; q++) acc[mt][nt][q] = 0.f;

    // per-lane ldmatrix offset within a 16x16 A tile
    const uint32_t a_lane_off = (uint32_t)(((lane & 15) * ASTR + (lane >> 4) * 8) * 2);
    const uint32_t* Bh = (const uint32_t*)(smem + BHI);
    const uint32_t* Bl = (const uint32_t*)(smem + BLO);

    for (int ch = 0; ch < NCH; ch++) {
        __syncthreads();   // previous chunk's A fully consumed
        // ---- load A chunk (128 rows x 64 k) into Ahi/Alo smem ----
        {
            int row  = tid >> 1;
            int half = tid & 1;
            int gr   = mbase + row;
            bool valid = gr < NN;
            uint32_t* dAh = (uint32_t*)(smem + AHI + row * (ASTR * 2));
            uint32_t* dAl = (uint32_t*)(smem + ALO + row * (ASTR * 2));
            if (LAYER == 1 && ch >= 2) {
                // convert x fp32 -> splits
                const float* src = X + (size_t)gr * 128 + (ch - 2) * 64 + half * 32;
#pragma unroll
                for (int j = 0; j < 8; j++) {
                    float4 v = make_float4(0.f, 0.f, 0.f, 0.f);
                    if (valid) v = *(const float4*)(src + j * 4);
                    uint32_t h0, l0, h1, l1;
                    split_pack(v.x, v.y, h0, l0);
                    split_pack(v.z, v.w, h1, l1);
                    int o = half * 16 + j * 2;
                    dAh[o] = h0; dAh[o + 1] = h1;
                    dAl[o] = l0; dAl[o + 1] = l1;
                }
            } else {
                const uint32_t* shi;
                const uint32_t* slo;
                if (LAYER == 1) { shi = g_mhi; slo = g_mlo; }
                else           { shi = g_hhi; slo = g_hlo; }
                size_t off = (size_t)gr * 64 + ch * 32 + half * 16;
#pragma unroll
                for (int j = 0; j < 4; j++) {
                    uint4 vh = make_uint4(0u, 0u, 0u, 0u), vl = vh;
                    if (valid) {
                        vh = *(const uint4*)(shi + off + j * 4);
                        vl = *(const uint4*)(slo + off + j * 4);
                    }
                    *(uint4*)(dAh + half * 16 + j * 4) = vh;
                    *(uint4*)(dAl + half * 16 + j * 4) = vl;
                }
            }
        }
        __syncthreads();

        // ---- compute 4 k-steps of 16 ----
#pragma unroll
        for (int ks = 0; ks < 4; ks++) {
            const int k0 = ks * 16;
            // B fragments for this kstep (4 n-tiles, hi+lo)
            uint32_t bh[4][2], bl[4][2];
#pragma unroll
            for (int nt = 0; nt < 4; nt++) {
                int n = wc * 32 + nt * 8 + (lane >> 2);
                int bi = n * (BSTR / 2) + (ch * 64 + k0) / 2 + (lane & 3);
                bh[nt][0] = Bh[bi];     bh[nt][1] = Bh[bi + 4];
                bl[nt][0] = Bl[bi];     bl[nt][1] = Bl[bi + 4];
            }
#pragma unroll
            for (int mt = 0; mt < 4; mt++) {
                uint32_t ahp = smem_base + AHI + (uint32_t)((wr * 64 + mt * 16) * ASTR + k0) * 2 + a_lane_off;
                uint32_t alp = ahp + (uint32_t)ALO;
                uint32_t ah[4], al[4];
                ldm_x4(ah, ahp);
                ldm_x4(al, alp);
#pragma unroll
                for (int nt = 0; nt < 4; nt++) {
                    mma_bf16(acc[mt][nt], ah, bh[nt][0], bh[nt][1]);
                    mma_bf16(acc[mt][nt], ah, bl[nt][0], bl[nt][1]);
                    mma_bf16(acc[mt][nt], al, bh[nt][0], bh[nt][1]);
                }
            }
        }
    }

    // ---- epilogue ----
#pragma unroll
    for (int nt = 0; nt < 4; nt++) {
        int col = wc * 32 + nt * 8 + (lane & 3) * 2;
        float bias0 = 0.f, bias1 = 0.f;
        if (LAYER == 1) {
            bias0 = __ldg(b1 + col);
            bias1 = __ldg(b1 + col + 1);
        } else if (col >= 64) {
            bias0 = __ldg(b2 + col - 64);
            bias1 = __ldg(b2 + col - 63);
        }
#pragma unroll
        for (int mt = 0; mt < 4; mt++) {
            int row0 = mbase + wr * 64 + mt * 16 + (lane >> 2);
#pragma unroll
            for (int hrow = 0; hrow < 2; hrow++) {
                int row = row0 + hrow * 8;
                if (row < NN) {
                    float v0 = acc[mt][nt][hrow * 2]     + bias0;
                    float v1 = acc[mt][nt][hrow * 2 + 1] + bias1;
                    if (LAYER == 1) {
                        v0 = fmaxf(v0, 0.f);
                        v1 = fmaxf(v1, 0.f);
                        uint32_t hi, lo;
                        split_pack(v0, v1, hi, lo);
                        g_hhi[(size_t)row * 64 + (col >> 1)] = hi;
                        g_hlo[(size_t)row * 64 + (col >> 1)] = lo;
                    } else {
                        *(float2*)(g_mean + (size_t)row * 128 + col) = make_float2(v0, v1);
                    }
                }
            }
        }
    }
}

// ======================= final: log_softmax(mean_agg(p) + q) =======================
__global__ void k_final(float* __restrict__ out) {
    int node = blockIdx.x * (blockDim.x >> 5) + (threadIdx.x >> 5);
    if (node >= NN) return;
    int lane = threadIdx.x & 31;
    int b = g_rowptr[node], e = g_rowptr[node + 1];
    float2 acc = make_float2(0.f, 0.f);
    const float* PQ = g_mean;
    int i = b;
    for (; i + 4 <= e; i += 4) {
        int u0 = g_col[i + 0], u1 = g_col[i + 1], u2 = g_col[i + 2], u3 = g_col[i + 3];
        float2 v0 = *((const float2*)(PQ + (size_t)u0 * 128) + lane);
        float2 v1 = *((const float2*)(PQ + (size_t)u1 * 128) + lane);
        float2 v2 = *((const float2*)(PQ + (size_t)u2 * 128) + lane);
        float2 v3 = *((const float2*)(PQ + (size_t)u3 * 128) + lane);
        acc.x += (v0.x + v1.x) + (v2.x + v3.x);
        acc.y += (v0.y + v1.y) + (v2.y + v3.y);
    }
    for (; i < e; i++) {
        int u = g_col[i];
        float2 v = *((const float2*)(PQ + (size_t)u * 128) + lane);
        acc.x += v.x; acc.y += v.y;
    }
    float inv = 1.f / (float)max(e - b, 1);
    float2 q = *((const float2*)(PQ + (size_t)node * 128 + 64) + lane);
    float r0 = acc.x * inv + q.x;
    float r1 = acc.y * inv + q.y;

    float mx = fmaxf(r0, r1);
#pragma unroll
    for (int off = 16; off > 0; off >>= 1)
        mx = fmaxf(mx, __shfl_xor_sync(0xffffffffu, mx, off));
    float se = expf(r0 - mx) + expf(r1 - mx);
#pragma unroll
    for (int off = 16; off > 0; off >>= 1)
        se += __shfl_xor_sync(0xffffffffu, se, off);
    float l = logf(se);
    float2 o = make_float2(r0 - mx - l, r1 - mx - l);
    *((float2*)(out + (size_t)node * CC) + lane) = o;
}

// ======================= launch =======================
extern "C" void kernel_launch(void* const* d_in, const int* in_sizes, int n_in,
                              void* d_out, int out_size) {
    const float* x   = (const float*)d_in[0];
    const int*   ei  = (const int*)d_in[1];
    const int*   src = ei;
    const int*   dst = ei + NE;
    const float* W1l = (const float*)d_in[2];
    const float* b1l = (const float*)d_in[3];
    const float* W1r = (const float*)d_in[4];
    const float* W2l = (const float*)d_in[5];
    const float* b2l = (const float*)d_in[6];
    const float* W2r = (const float*)d_in[7];
    float* out = (float*)d_out;

    // smem sizes
    const int SMEM1 = 36864 + 2 * (128 * (256 + 8) * 2);   // 36864 + 135168 = 172032
    const int SMEM2 = 36864 + 2 * (128 * (128 + 8) * 2);   // 36864 + 69632  = 106496
    static bool attr_done = false;
    if (!attr_done) {
        cudaFuncSetAttribute(k_mmagemm<1>, cudaFuncAttributeMaxDynamicSharedMemorySize, SMEM1);
        cudaFuncSetAttribute(k_mmagemm<2>, cudaFuncAttributeMaxDynamicSharedMemorySize, SMEM2);
        attr_done = true;
    }

    // weight prep (independent of CSR)
    k_prepW<<<(128 * 256 + 128 * 128 + 255) / 256, 256>>>(W1l, W1r, W2l, W2r);

    // CSR build (by destination)
    k_zero_cnt<<<(NN + 255) / 256, 256>>>();
    k_count<<<(NE + 255) / 256, 256>>>(dst);
    k_scan<<<1, 1024>>>();
    k_fill<<<(NE + 255) / 256, 256>>>(src, dst);

    // layer 1
    k_agg128<<<(NN + 7) / 8, 256>>>(x);                          // g_mhi/g_mlo = mean(x) splits
    k_mmagemm<1><<<(NN + 127) / 128, 256, SMEM1>>>(x, b1l, b2l); // h -> g_hhi/g_hlo

    // layer 2 (project before aggregating: mean commutes with linear map)
    k_mmagemm<2><<<(NN + 127) / 128, 256, SMEM2>>>(x, b1l, b2l); // g_mean = [p | q]
    k_final<<<(NN + 7) / 8, 256>>>(out);
}

// round 5
// speedup vs baseline: 1.7979x; 1.4720x over previous
#include <cuda_runtime.h>
#include <cuda_bf16.h>
#include <cstdint>

#define NN 100000
#define NE 1600000
#define FF 128
#define CC 64
#define SCAN_B 1024
#define SCAN_NB ((NN + SCAN_B - 1) / SCAN_B)   // 98

// ======================= scratch (static device globals) =======================
__device__ int   g_cnt[NN];
__device__ int   g_rowptr[NN + 1];
__device__ int   g_cursor[NN];
__device__ int   g_blksum[SCAN_NB];
__device__ int   g_col[NE];
__device__ float g_mean[(size_t)NN * 128];     // PQ output of layer2 (for k_final)
__device__ uint32_t g_mhi[(size_t)NN * 64];    // mean(x) packed bf16x2 hi
__device__ uint32_t g_mlo[(size_t)NN * 64];    // mean(x) packed bf16x2 lo
__device__ uint32_t g_hhi[(size_t)NN * 64];    // h packed bf16x2 hi
__device__ uint32_t g_hlo[(size_t)NN * 64];    // h packed bf16x2 lo
// weights as bf16 hi/lo, row-major [n][k]
__device__ unsigned short g_w1hi[128 * 256];
__device__ unsigned short g_w1lo[128 * 256];
__device__ unsigned short g_w2hi[128 * 128];
__device__ unsigned short g_w2lo[128 * 128];

// ======================= small helpers =======================
__device__ __forceinline__ uint32_t smem_to_u32(const void* p) {
    uint32_t a;
    asm("{ .reg .u64 t; cvta.to.shared.u64 t, %1; cvt.u32.u64 %0, t; }" : "=r"(a) : "l"(p));
    return a;
}

__device__ __forceinline__ void ldm_x4(uint32_t* r, uint32_t addr) {
    asm volatile("ldmatrix.sync.aligned.m8n8.x4.shared.b16 {%0,%1,%2,%3}, [%4];"
                 : "=r"(r[0]), "=r"(r[1]), "=r"(r[2]), "=r"(r[3]) : "r"(addr));
}

__device__ __forceinline__ void mma_bf16(float* d, const uint32_t* a, uint32_t b0, uint32_t b1) {
    asm volatile(
        "mma.sync.aligned.m16n8k16.row.col.f32.bf16.bf16.f32 "
        "{%0,%1,%2,%3}, {%4,%5,%6,%7}, {%8,%9}, {%0,%1,%2,%3};"
        : "+f"(d[0]), "+f"(d[1]), "+f"(d[2]), "+f"(d[3])
        : "r"(a[0]), "r"(a[1]), "r"(a[2]), "r"(a[3]), "r"(b0), "r"(b1));
}

__device__ __forceinline__ void split_pack(float a, float b, uint32_t& hi, uint32_t& lo) {
    __nv_bfloat16 ah = __float2bfloat16(a), bh = __float2bfloat16(b);
    float ar = a - __bfloat162float(ah);
    float br = b - __bfloat162float(bh);
    hi = (uint32_t)__bfloat16_as_ushort(ah) | ((uint32_t)__bfloat16_as_ushort(bh) << 16);
    lo = (uint32_t)__bfloat16_as_ushort(__float2bfloat16(ar))
       | ((uint32_t)__bfloat16_as_ushort(__float2bfloat16(br)) << 16);
}

// ======================= CSR build =======================
__global__ void k_zero_cnt() {
    int i = blockIdx.x * blockDim.x + threadIdx.x;
    if (i < NN) g_cnt[i] = 0;
}

__global__ void k_count(const int* __restrict__ dst) {
    int e = blockIdx.x * blockDim.x + threadIdx.x;
    if (e < NE) atomicAdd(&g_cnt[dst[e]], 1);
}

// phase 1: per-block exclusive scan of g_cnt -> g_rowptr (local), block total -> g_blksum
__global__ void k_scan1() {
    __shared__ int sh[SCAN_B];
    int t = threadIdx.x;
    int i = blockIdx.x * SCAN_B + t;
    int v = (i < NN) ? g_cnt[i] : 0;
    sh[t] = v;
    __syncthreads();
#pragma unroll
    for (int off = 1; off < SCAN_B; off <<= 1) {
        int u = (t >= off) ? sh[t - off] : 0;
        __syncthreads();
        sh[t] += u;
        __syncthreads();
    }
    if (i < NN) g_rowptr[i] = sh[t] - v;          // local exclusive prefix
    if (t == SCAN_B - 1) g_blksum[blockIdx.x] = sh[t];
}

// phase 2: scan block sums (98 values) in one small block
__global__ void k_scan2() {
    __shared__ int sh[128];
    int t = threadIdx.x;
    int v = (t < SCAN_NB) ? g_blksum[t] : 0;
    sh[t] = v;
    __syncthreads();
#pragma unroll
    for (int off = 1; off < 128; off <<= 1) {
        int u = (t >= off) ? sh[t - off] : 0;
        __syncthreads();
        sh[t] += u;
        __syncthreads();
    }
    if (t < SCAN_NB) g_blksum[t] = sh[t] - v;     // exclusive block offsets
}

// phase 3: add block offset, init cursor, set rowptr[NN]
__global__ void k_scan3() {
    int i = blockIdx.x * SCAN_B + threadIdx.x;
    if (i < NN) {
        int r = g_rowptr[i] + g_blksum[blockIdx.x];
        g_rowptr[i] = r;
        g_cursor[i] = r;
    }
    if (i == 0) g_rowptr[NN] = NE;
}

__global__ void k_fill(const int* __restrict__ src, const int* __restrict__ dst) {
    int e = blockIdx.x * blockDim.x + threadIdx.x;
    if (e < NE) {
        int d = dst[e];
        int pos = atomicAdd(&g_cursor[d], 1);
        g_col[pos] = src[e];
    }
}

// ======================= aggregation (warp per node) -> bf16 splits =======================
__global__ void k_agg128(const float* __restrict__ X) {
    int node = blockIdx.x * (blockDim.x >> 5) + (threadIdx.x >> 5);
    if (node >= NN) return;
    int lane = threadIdx.x & 31;
    int b = g_rowptr[node], e = g_rowptr[node + 1];
    float4 acc = make_float4(0.f, 0.f, 0.f, 0.f);
    int i = b;
    for (; i + 4 <= e; i += 4) {
        int u0 = g_col[i + 0], u1 = g_col[i + 1], u2 = g_col[i + 2], u3 = g_col[i + 3];
        float4 v0 = *((const float4*)(X + (size_t)u0 * FF) + lane);
        float4 v1 = *((const float4*)(X + (size_t)u1 * FF) + lane);
        float4 v2 = *((const float4*)(X + (size_t)u2 * FF) + lane);
        float4 v3 = *((const float4*)(X + (size_t)u3 * FF) + lane);
        acc.x += (v0.x + v1.x) + (v2.x + v3.x);
        acc.y += (v0.y + v1.y) + (v2.y + v3.y);
        acc.z += (v0.z + v1.z) + (v2.z + v3.z);
        acc.w += (v0.w + v1.w) + (v2.w + v3.w);
    }
    for (; i < e; i++) {
        int u = g_col[i];
        float4 v = *((const float4*)(X + (size_t)u * FF) + lane);
        acc.x += v.x; acc.y += v.y; acc.z += v.z; acc.w += v.w;
    }
    float inv = 1.f / (float)max(e - b, 1);
    uint32_t h0, l0, h1, l1;
    split_pack(acc.x * inv, acc.y * inv, h0, l0);
    split_pack(acc.z * inv, acc.w * inv, h1, l1);
    uint32_t* dh = g_mhi + (size_t)node * 64 + lane * 2;
    uint32_t* dl = g_mlo + (size_t)node * 64 + lane * 2;
    dh[0] = h0; dh[1] = h1;
    dl[0] = l0; dl[1] = l1;
}

// ======================= weight prep: fp32 -> bf16 hi/lo row-major =======================
__global__ void k_prepW(const float* __restrict__ W1l, const float* __restrict__ W1r,
                        const float* __restrict__ W2l, const float* __restrict__ W2r) {
    int idx = blockIdx.x * blockDim.x + threadIdx.x;
    if (idx < 128 * 256) {
        int n = idx >> 8, k = idx & 255;
        float w = (k < 128) ? W1l[n * 128 + k] : W1r[n * 128 + (k - 128)];
        __nv_bfloat16 h = __float2bfloat16(w);
        g_w1hi[idx] = __bfloat16_as_ushort(h);
        g_w1lo[idx] = __bfloat16_as_ushort(__float2bfloat16(w - __bfloat162float(h)));
    } else {
        int i2 = idx - 128 * 256;
        if (i2 < 128 * 128) {
            int n = i2 >> 7, k = i2 & 127;
            float w = (n < 64) ? W2l[n * 128 + k] : W2r[(n - 64) * 128 + k];
            __nv_bfloat16 h = __float2bfloat16(w);
            g_w2hi[i2] = __bfloat16_as_ushort(h);
            g_w2lo[i2] = __bfloat16_as_ushort(__float2bfloat16(w - __bfloat162float(h)));
        }
    }
}

// ======================= HMMA GEMM =======================
// LAYER 1: D[128x128] = [mean|x][128x256] @ W1cat^T  -> h (bias+relu) packed bf16 hi/lo
// LAYER 2: D[128x128] = h[128x128] @ [W2l;W2r]^T     -> PQ fp32 (+b2l on cols 64..127)
// 3-term split: D = Ahi*Bhi + Ahi*Blo + Alo*Bhi
#define ASTR 72   // bf16 elements per A smem row (144B: 16B-aligned, ldmatrix conflict-free)

template <int LAYER>
__global__ void __launch_bounds__(256, 1)
k_mmagemm(const float* __restrict__ X, const float* __restrict__ b1,
          const float* __restrict__ b2)
{
    constexpr int K     = (LAYER == 1) ? 256 : 128;
    constexpr int NCH   = K / 64;            // K chunks of 64
    constexpr int BSTR  = K + 8;             // bf16 per B smem row (pad: conflict-free frag LDS)
    constexpr int AHI   = 0;
    constexpr int ALO   = 128 * ASTR * 2;    // 18432
    constexpr int BHI   = 2 * 128 * ASTR * 2;  // 36864
    constexpr int BSPL  = 128 * BSTR * 2;
    constexpr int BLO   = BHI + BSPL;

    extern __shared__ char smem[];
    const uint32_t smem_base = smem_to_u32(smem);
    const int tid  = threadIdx.x;
    const int warp = tid >> 5;
    const int lane = tid & 31;
    const int wr   = warp >> 2;   // 0..1 : 64-row half
    const int wc   = warp & 3;    // 0..3 : 32-col quarter
    const int mbase = blockIdx.x * 128;

    // ---- copy W (hi/lo) into smem, padded stride ----
    {
        const uint4* shi = (LAYER == 1) ? (const uint4*)g_w1hi : (const uint4*)g_w2hi;
        const uint4* slo = (LAYER == 1) ? (const uint4*)g_w1lo : (const uint4*)g_w2lo;
        const int rowv = K / 8;  // uint4 per source row
        for (int i = tid; i < 128 * rowv; i += 256) {
            int n = i / rowv, c = i - n * rowv;
            *(uint4*)(smem + BHI + n * (BSTR * 2) + c * 16) = shi[i];
            *(uint4*)(smem + BLO + n * (BSTR * 2) + c * 16) = slo[i];
        }
    }

    float acc[4][4][4];
#pragma unroll
    for (int mt = 0; mt < 4; mt++)
#pragma unroll
        for (int nt = 0; nt < 4; nt++)
#pragma unroll
            for (int q = 0; q < 4; q++) acc[mt][nt][q] = 0.f;

    // per-lane ldmatrix offset within a 16x16 A tile
    const uint32_t a_lane_off = (uint32_t)(((lane & 15) * ASTR + (lane >> 4) * 8) * 2);
    const uint32_t* Bh = (const uint32_t*)(smem + BHI);
    const uint32_t* Bl = (const uint32_t*)(smem + BLO);

    for (int ch = 0; ch < NCH; ch++) {
        __syncthreads();   // previous chunk's A fully consumed
        // ---- load A chunk (128 rows x 64 k) into Ahi/Alo smem ----
        {
            int row  = tid >> 1;
            int half = tid & 1;
            int gr   = mbase + row;
            bool valid = gr < NN;
            uint32_t* dAh = (uint32_t*)(smem + AHI + row * (ASTR * 2));
            uint32_t* dAl = (uint32_t*)(smem + ALO + row * (ASTR * 2));
            if (LAYER == 1 && ch >= 2) {
                // convert x fp32 -> splits
                const float* src = X + (size_t)gr * 128 + (ch - 2) * 64 + half * 32;
#pragma unroll
                for (int j = 0; j < 8; j++) {
                    float4 v = make_float4(0.f, 0.f, 0.f, 0.f);
                    if (valid) v = *(const float4*)(src + j * 4);
                    uint32_t h0, l0, h1, l1;
                    split_pack(v.x, v.y, h0, l0);
                    split_pack(v.z, v.w, h1, l1);
                    int o = half * 16 + j * 2;
                    dAh[o] = h0; dAh[o + 1] = h1;
                    dAl[o] = l0; dAl[o + 1] = l1;
                }
            } else {
                const uint32_t* shi;
                const uint32_t* slo;
                if (LAYER == 1) { shi = g_mhi; slo = g_mlo; }
                else           { shi = g_hhi; slo = g_hlo; }
                size_t off = (size_t)gr * 64 + ch * 32 + half * 16;
#pragma unroll
                for (int j = 0; j < 4; j++) {
                    uint4 vh = make_uint4(0u, 0u, 0u, 0u), vl = vh;
                    if (valid) {
                        vh = *(const uint4*)(shi + off + j * 4);
                        vl = *(const uint4*)(slo + off + j * 4);
                    }
                    *(uint4*)(dAh + half * 16 + j * 4) = vh;
                    *(uint4*)(dAl + half * 16 + j * 4) = vl;
                }
            }
        }
        __syncthreads();

        // ---- compute 4 k-steps of 16 ----
#pragma unroll
        for (int ks = 0; ks < 4; ks++) {
            const int k0 = ks * 16;
            // B fragments for this kstep (4 n-tiles, hi+lo)
            uint32_t bh[4][2], bl[4][2];
#pragma unroll
            for (int nt = 0; nt < 4; nt++) {
                int n = wc * 32 + nt * 8 + (lane >> 2);
                int bi = n * (BSTR / 2) + (ch * 64 + k0) / 2 + (lane & 3);
                bh[nt][0] = Bh[bi];     bh[nt][1] = Bh[bi + 4];
                bl[nt][0] = Bl[bi];     bl[nt][1] = Bl[bi + 4];
            }
#pragma unroll
            for (int mt = 0; mt < 4; mt++) {
                uint32_t ahp = smem_base + AHI + (uint32_t)((wr * 64 + mt * 16) * ASTR + k0) * 2 + a_lane_off;
                uint32_t alp = ahp + (uint32_t)ALO;
                uint32_t ah[4], al[4];
                ldm_x4(ah, ahp);
                ldm_x4(al, alp);
#pragma unroll
                for (int nt = 0; nt < 4; nt++) {
                    mma_bf16(acc[mt][nt], ah, bh[nt][0], bh[nt][1]);
                    mma_bf16(acc[mt][nt], ah, bl[nt][0], bl[nt][1]);
                    mma_bf16(acc[mt][nt], al, bh[nt][0], bh[nt][1]);
                }
            }
        }
    }

    // ---- epilogue ----
#pragma unroll
    for (int nt = 0; nt < 4; nt++) {
        int col = wc * 32 + nt * 8 + (lane & 3) * 2;
        float bias0 = 0.f, bias1 = 0.f;
        if (LAYER == 1) {
            bias0 = __ldg(b1 + col);
            bias1 = __ldg(b1 + col + 1);
        } else if (col >= 64) {
            bias0 = __ldg(b2 + col - 64);
            bias1 = __ldg(b2 + col - 63);
        }
#pragma unroll
        for (int mt = 0; mt < 4; mt++) {
            int row0 = mbase + wr * 64 + mt * 16 + (lane >> 2);
#pragma unroll
            for (int hrow = 0; hrow < 2; hrow++) {
                int row = row0 + hrow * 8;
                if (row < NN) {
                    float v0 = acc[mt][nt][hrow * 2]     + bias0;
                    float v1 = acc[mt][nt][hrow * 2 + 1] + bias1;
                    if (LAYER == 1) {
                        v0 = fmaxf(v0, 0.f);
                        v1 = fmaxf(v1, 0.f);
                        uint32_t hi, lo;
                        split_pack(v0, v1, hi, lo);
                        g_hhi[(size_t)row * 64 + (col >> 1)] = hi;
                        g_hlo[(size_t)row * 64 + (col >> 1)] = lo;
                    } else {
                        *(float2*)(g_mean + (size_t)row * 128 + col) = make_float2(v0, v1);
                    }
                }
            }
        }
    }
}

// ======================= final: log_softmax(mean_agg(p) + q) =======================
__global__ void k_final(float* __restrict__ out) {
    int node = blockIdx.x * (blockDim.x >> 5) + (threadIdx.x >> 5);
    if (node >= NN) return;
    int lane = threadIdx.x & 31;
    int b = g_rowptr[node], e = g_rowptr[node + 1];
    float2 acc = make_float2(0.f, 0.f);
    const float* PQ = g_mean;
    int i = b;
    for (; i + 4 <= e; i += 4) {
        int u0 = g_col[i + 0], u1 = g_col[i + 1], u2 = g_col[i + 2], u3 = g_col[i + 3];
        float2 v0 = *((const float2*)(PQ + (size_t)u0 * 128) + lane);
        float2 v1 = *((const float2*)(PQ + (size_t)u1 * 128) + lane);
        float2 v2 = *((const float2*)(PQ + (size_t)u2 * 128) + lane);
        float2 v3 = *((const float2*)(PQ + (size_t)u3 * 128) + lane);
        acc.x += (v0.x + v1.x) + (v2.x + v3.x);
        acc.y += (v0.y + v1.y) + (v2.y + v3.y);
    }
    for (; i < e; i++) {
        int u = g_col[i];
        float2 v = *((const float2*)(PQ + (size_t)u * 128) + lane);
        acc.x += v.x; acc.y += v.y;
    }
    float inv = 1.f / (float)max(e - b, 1);
    float2 q = *((const float2*)(PQ + (size_t)node * 128 + 64) + lane);
    float r0 = acc.x * inv + q.x;
    float r1 = acc.y * inv + q.y;

    float mx = fmaxf(r0, r1);
#pragma unroll
    for (int off = 16; off > 0; off >>= 1)
        mx = fmaxf(mx, __shfl_xor_sync(0xffffffffu, mx, off));
    float se = expf(r0 - mx) + expf(r1 - mx);
#pragma unroll
    for (int off = 16; off > 0; off >>= 1)
        se += __shfl_xor_sync(0xffffffffu, se, off);
    float l = logf(se);
    float2 o = make_float2(r0 - mx - l, r1 - mx - l);
    *((float2*)(out + (size_t)node * CC) + lane) = o;
}

// ======================= launch =======================
extern "C" void kernel_launch(void* const* d_in, const int* in_sizes, int n_in,
                              void* d_out, int out_size) {
    const float* x   = (const float*)d_in[0];
    const int*   ei  = (const int*)d_in[1];
    const int*   src = ei;
    const int*   dst = ei + NE;
    const float* W1l = (const float*)d_in[2];
    const float* b1l = (const float*)d_in[3];
    const float* W1r = (const float*)d_in[4];
    const float* W2l = (const float*)d_in[5];
    const float* b2l = (const float*)d_in[6];
    const float* W2r = (const float*)d_in[7];
    float* out = (float*)d_out;

    // smem sizes
    const int SMEM1 = 36864 + 2 * (128 * (256 + 8) * 2);   // 172032
    const int SMEM2 = 36864 + 2 * (128 * (128 + 8) * 2);   // 106496
    static bool attr_done = false;
    if (!attr_done) {
        cudaFuncSetAttribute(k_mmagemm<1>, cudaFuncAttributeMaxDynamicSharedMemorySize, SMEM1);
        cudaFuncSetAttribute(k_mmagemm<2>, cudaFuncAttributeMaxDynamicSharedMemorySize, SMEM2);
        attr_done = true;
    }

    // weight prep (independent of CSR)
    k_prepW<<<(128 * 256 + 128 * 128 + 255) / 256, 256>>>(W1l, W1r, W2l, W2r);

    // CSR build (by destination) — parallel 3-phase scan
    k_zero_cnt<<<(NN + 255) / 256, 256>>>();
    k_count<<<(NE + 255) / 256, 256>>>(dst);
    k_scan1<<<SCAN_NB, SCAN_B>>>();
    k_scan2<<<1, 128>>>();
    k_scan3<<<SCAN_NB, SCAN_B>>>();
    k_fill<<<(NE + 255) / 256, 256>>>(src, dst);

    // layer 1
    k_agg128<<<(NN + 7) / 8, 256>>>(x);                          // g_mhi/g_mlo = mean(x) splits
    k_mmagemm<1><<<(NN + 127) / 128, 256, SMEM1>>>(x, b1l, b2l); // h -> g_hhi/g_hlo

    // layer 2 (project before aggregating: mean commutes with linear map)
    k_mmagemm<2><<<(NN + 127) / 128, 256, SMEM2>>>(x, b1l, b2l); // g_mean = [p | q]
    k_final<<<(NN + 7) / 8, 256>>>(out);
}

// round 6
// speedup vs baseline: 1.8552x; 1.0319x over previous
#include <cuda_runtime.h>
#include <cuda_bf16.h>
#include <cstdint>

#define NN 100000
#define NE 1600000
#define FF 128
#define CC 64
#define SCAN_B 1024
#define SCAN_NB ((NN + SCAN_B - 1) / SCAN_B)   // 98

// ======================= scratch (static device globals) =======================
__device__ int   g_cnt[NN];
__device__ int   g_rowptr[NN + 1];
__device__ int   g_cursor[NN];
__device__ int   g_blksum[SCAN_NB];
__device__ int   g_col[NE];
__device__ float g_mean[(size_t)NN * 128];     // PQ output of layer2 (for k_final)
__device__ float g_xr[(size_t)NN * 128];       // x @ W1r^T (computed on side stream)
__device__ uint32_t g_mhi[(size_t)NN * 64];    // mean(x) packed bf16x2 hi
__device__ uint32_t g_mlo[(size_t)NN * 64];    // mean(x) packed bf16x2 lo
__device__ uint32_t g_hhi[(size_t)NN * 64];    // h packed bf16x2 hi
__device__ uint32_t g_hlo[(size_t)NN * 64];    // h packed bf16x2 lo
// weights as bf16 hi/lo, row-major [n][k]
__device__ unsigned short g_w1hi[128 * 256];
__device__ unsigned short g_w1lo[128 * 256];
__device__ unsigned short g_w2hi[128 * 128];
__device__ unsigned short g_w2lo[128 * 128];

// ======================= small helpers =======================
__device__ __forceinline__ uint32_t smem_to_u32(const void* p) {
    uint32_t a;
    asm("{ .reg .u64 t; cvta.to.shared.u64 t, %1; cvt.u32.u64 %0, t; }" : "=r"(a) : "l"(p));
    return a;
}

__device__ __forceinline__ void ldm_x4(uint32_t* r, uint32_t addr) {
    asm volatile("ldmatrix.sync.aligned.m8n8.x4.shared.b16 {%0,%1,%2,%3}, [%4];"
                 : "=r"(r[0]), "=r"(r[1]), "=r"(r[2]), "=r"(r[3]) : "r"(addr));
}

__device__ __forceinline__ void mma_bf16(float* d, const uint32_t* a, uint32_t b0, uint32_t b1) {
    asm volatile(
        "mma.sync.aligned.m16n8k16.row.col.f32.bf16.bf16.f32 "
        "{%0,%1,%2,%3}, {%4,%5,%6,%7}, {%8,%9}, {%0,%1,%2,%3};"
        : "+f"(d[0]), "+f"(d[1]), "+f"(d[2]), "+f"(d[3])
        : "r"(a[0]), "r"(a[1]), "r"(a[2]), "r"(a[3]), "r"(b0), "r"(b1));
}

__device__ __forceinline__ void split_pack(float a, float b, uint32_t& hi, uint32_t& lo) {
    __nv_bfloat16 ah = __float2bfloat16(a), bh = __float2bfloat16(b);
    float ar = a - __bfloat162float(ah);
    float br = b - __bfloat162float(bh);
    hi = (uint32_t)__bfloat16_as_ushort(ah) | ((uint32_t)__bfloat16_as_ushort(bh) << 16);
    lo = (uint32_t)__bfloat16_as_ushort(__float2bfloat16(ar))
       | ((uint32_t)__bfloat16_as_ushort(__float2bfloat16(br)) << 16);
}

// ======================= CSR build =======================
__global__ void k_zero_cnt() {
    int i = blockIdx.x * blockDim.x + threadIdx.x;
    if (i < NN) g_cnt[i] = 0;
}

__global__ void k_count(const int* __restrict__ dst) {
    int e = blockIdx.x * blockDim.x + threadIdx.x;
    if (e < NE) atomicAdd(&g_cnt[dst[e]], 1);
}

__global__ void k_scan1() {
    __shared__ int sh[SCAN_B];
    int t = threadIdx.x;
    int i = blockIdx.x * SCAN_B + t;
    int v = (i < NN) ? g_cnt[i] : 0;
    sh[t] = v;
    __syncthreads();
#pragma unroll
    for (int off = 1; off < SCAN_B; off <<= 1) {
        int u = (t >= off) ? sh[t - off] : 0;
        __syncthreads();
        sh[t] += u;
        __syncthreads();
    }
    if (i < NN) g_rowptr[i] = sh[t] - v;
    if (t == SCAN_B - 1) g_blksum[blockIdx.x] = sh[t];
}

__global__ void k_scan2() {
    __shared__ int sh[128];
    int t = threadIdx.x;
    int v = (t < SCAN_NB) ? g_blksum[t] : 0;
    sh[t] = v;
    __syncthreads();
#pragma unroll
    for (int off = 1; off < 128; off <<= 1) {
        int u = (t >= off) ? sh[t - off] : 0;
        __syncthreads();
        sh[t] += u;
        __syncthreads();
    }
    if (t < SCAN_NB) g_blksum[t] = sh[t] - v;
}

__global__ void k_scan3() {
    int i = blockIdx.x * SCAN_B + threadIdx.x;
    if (i < NN) {
        int r = g_rowptr[i] + g_blksum[blockIdx.x];
        g_rowptr[i] = r;
        g_cursor[i] = r;
    }
    if (i == 0) g_rowptr[NN] = NE;
}

__global__ void k_fill(const int* __restrict__ src, const int* __restrict__ dst) {
    int e = blockIdx.x * blockDim.x + threadIdx.x;
    if (e < NE) {
        int d = dst[e];
        int pos = atomicAdd(&g_cursor[d], 1);
        g_col[pos] = src[e];
    }
}

// ======================= aggregation (warp per node) -> bf16 splits =======================
__global__ void k_agg128(const float* __restrict__ X) {
    int node = blockIdx.x * (blockDim.x >> 5) + (threadIdx.x >> 5);
    if (node >= NN) return;
    int lane = threadIdx.x & 31;
    int b = g_rowptr[node], e = g_rowptr[node + 1];
    float4 acc = make_float4(0.f, 0.f, 0.f, 0.f);
    int i = b;
    for (; i + 4 <= e; i += 4) {
        int u0 = g_col[i + 0], u1 = g_col[i + 1], u2 = g_col[i + 2], u3 = g_col[i + 3];
        float4 v0 = *((const float4*)(X + (size_t)u0 * FF) + lane);
        float4 v1 = *((const float4*)(X + (size_t)u1 * FF) + lane);
        float4 v2 = *((const float4*)(X + (size_t)u2 * FF) + lane);
        float4 v3 = *((const float4*)(X + (size_t)u3 * FF) + lane);
        acc.x += (v0.x + v1.x) + (v2.x + v3.x);
        acc.y += (v0.y + v1.y) + (v2.y + v3.y);
        acc.z += (v0.z + v1.z) + (v2.z + v3.z);
        acc.w += (v0.w + v1.w) + (v2.w + v3.w);
    }
    for (; i < e; i++) {
        int u = g_col[i];
        float4 v = *((const float4*)(X + (size_t)u * FF) + lane);
        acc.x += v.x; acc.y += v.y; acc.z += v.z; acc.w += v.w;
    }
    float inv = 1.f / (float)max(e - b, 1);
    uint32_t h0, l0, h1, l1;
    split_pack(acc.x * inv, acc.y * inv, h0, l0);
    split_pack(acc.z * inv, acc.w * inv, h1, l1);
    uint32_t* dh = g_mhi + (size_t)node * 64 + lane * 2;
    uint32_t* dl = g_mlo + (size_t)node * 64 + lane * 2;
    dh[0] = h0; dh[1] = h1;
    dl[0] = l0; dl[1] = l1;
}

// ======================= weight prep: fp32 -> bf16 hi/lo row-major =======================
__global__ void k_prepW(const float* __restrict__ W1l, const float* __restrict__ W1r,
                        const float* __restrict__ W2l, const float* __restrict__ W2r) {
    int idx = blockIdx.x * blockDim.x + threadIdx.x;
    if (idx < 128 * 256) {
        int n = idx >> 8, k = idx & 255;
        float w = (k < 128) ? W1l[n * 128 + k] : W1r[n * 128 + (k - 128)];
        __nv_bfloat16 h = __float2bfloat16(w);
        g_w1hi[idx] = __bfloat16_as_ushort(h);
        g_w1lo[idx] = __bfloat16_as_ushort(__float2bfloat16(w - __bfloat162float(h)));
    } else {
        int i2 = idx - 128 * 256;
        if (i2 < 128 * 128) {
            int n = i2 >> 7, k = i2 & 127;
            float w = (n < 64) ? W2l[n * 128 + k] : W2r[(n - 64) * 128 + k];
            __nv_bfloat16 h = __float2bfloat16(w);
            g_w2hi[i2] = __bfloat16_as_ushort(h);
            g_w2lo[i2] = __bfloat16_as_ushort(__float2bfloat16(w - __bfloat162float(h)));
        }
    }
}

// ======================= HMMA GEMM (all K=128) =======================
// LAYER 0: xr = x @ W1r^T                  -> g_xr fp32        (side stream)
// LAYER 1: h  = relu(mean @ W1l^T + xr+b1) -> g_hhi/g_hlo
// LAYER 2: PQ = h @ [W2l;W2r]^T (+b2 hi)   -> g_mean fp32
// 3-term split: D = Ahi*Bhi + Ahi*Blo + Alo*Bhi
#define ASTR 72   // bf16 per A smem row (144B: 16B-aligned, ldmatrix conflict-free)
#define BSTR 136  // bf16 per B smem row (pad: conflict-free frag LDS)

template <int LAYER>
__global__ void __launch_bounds__(256, 2)
k_mmagemm(const float* __restrict__ X, const float* __restrict__ b1,
          const float* __restrict__ b2)
{
    constexpr int AHI   = 0;
    constexpr int ALO   = 128 * ASTR * 2;      // 18432
    constexpr int BHI   = 2 * 128 * ASTR * 2;  // 36864
    constexpr int BSPL  = 128 * BSTR * 2;      // 34816
    constexpr int BLO   = BHI + BSPL;
    // smem total = 36864 + 69632 = 106496

    extern __shared__ char smem[];
    const uint32_t smem_base = smem_to_u32(smem);
    const int tid  = threadIdx.x;
    const int warp = tid >> 5;
    const int lane = tid & 31;
    const int wr   = warp >> 2;   // 0..1 : 64-row half
    const int wc   = warp & 3;    // 0..3 : 32-col quarter
    const int mbase = blockIdx.x * 128;

    // ---- copy W (hi/lo) into smem, padded stride ----
    {
        const uint4* shi;
        const uint4* slo;
        int srowv, woff8;
        if (LAYER <= 1) {
            shi = (const uint4*)g_w1hi; slo = (const uint4*)g_w1lo;
            srowv = 32; woff8 = (LAYER == 0) ? 16 : 0;   // k offset 128 for W1r half
        } else {
            shi = (const uint4*)g_w2hi; slo = (const uint4*)g_w2lo;
            srowv = 16; woff8 = 0;
        }
        for (int i = tid; i < 128 * 16; i += 256) {
            int n = i >> 4, c = i & 15;
            *(uint4*)(smem + BHI + n * (BSTR * 2) + c * 16) = shi[n * srowv + woff8 + c];
            *(uint4*)(smem + BLO + n * (BSTR * 2) + c * 16) = slo[n * srowv + woff8 + c];
        }
    }

    float acc[4][4][4];
#pragma unroll
    for (int mt = 0; mt < 4; mt++)
#pragma unroll
        for (int nt = 0; nt < 4; nt++)
#pragma unroll
            for (int q = 0; q < 4; q++) acc[mt][nt][q] = 0.f;

    const uint32_t a_lane_off = (uint32_t)(((lane & 15) * ASTR + (lane >> 4) * 8) * 2);
    const uint32_t* Bh = (const uint32_t*)(smem + BHI);
    const uint32_t* Bl = (const uint32_t*)(smem + BLO);

#pragma unroll
    for (int ch = 0; ch < 2; ch++) {
        __syncthreads();
        // ---- load A chunk (128 rows x 64 k) into Ahi/Alo smem ----
        {
            int row  = tid >> 1;
            int half = tid & 1;
            int gr   = mbase + row;
            bool valid = gr < NN;
            uint32_t* dAh = (uint32_t*)(smem + AHI + row * (ASTR * 2));
            uint32_t* dAl = (uint32_t*)(smem + ALO + row * (ASTR * 2));
            if (LAYER == 0) {
                const float* src = X + (size_t)gr * 128 + ch * 64 + half * 32;
#pragma unroll
                for (int j = 0; j < 8; j++) {
                    float4 v = make_float4(0.f, 0.f, 0.f, 0.f);
                    if (valid) v = *(const float4*)(src + j * 4);
                    uint32_t h0, l0, h1, l1;
                    split_pack(v.x, v.y, h0, l0);
                    split_pack(v.z, v.w, h1, l1);
                    int o = half * 16 + j * 2;
                    dAh[o] = h0; dAh[o + 1] = h1;
                    dAl[o] = l0; dAl[o + 1] = l1;
                }
            } else {
                const uint32_t* shi = (LAYER == 1) ? g_mhi : g_hhi;
                const uint32_t* slo = (LAYER == 1) ? g_mlo : g_hlo;
                size_t off = (size_t)gr * 64 + ch * 32 + half * 16;
#pragma unroll
                for (int j = 0; j < 4; j++) {
                    uint4 vh = make_uint4(0u, 0u, 0u, 0u), vl = vh;
                    if (valid) {
                        vh = *(const uint4*)(shi + off + j * 4);
                        vl = *(const uint4*)(slo + off + j * 4);
                    }
                    *(uint4*)(dAh + half * 16 + j * 4) = vh;
                    *(uint4*)(dAl + half * 16 + j * 4) = vl;
                }
            }
        }
        __syncthreads();

        // ---- compute 4 k-steps of 16 ----
#pragma unroll
        for (int ks = 0; ks < 4; ks++) {
            const int k0 = ks * 16;
            uint32_t bh[4][2], bl[4][2];
#pragma unroll
            for (int nt = 0; nt < 4; nt++) {
                int n = wc * 32 + nt * 8 + (lane >> 2);
                int bi = n * (BSTR / 2) + (ch * 64 + k0) / 2 + (lane & 3);
                bh[nt][0] = Bh[bi];     bh[nt][1] = Bh[bi + 4];
                bl[nt][0] = Bl[bi];     bl[nt][1] = Bl[bi + 4];
            }
#pragma unroll
            for (int mt = 0; mt < 4; mt++) {
                uint32_t ahp = smem_base + AHI + (uint32_t)((wr * 64 + mt * 16) * ASTR + k0) * 2 + a_lane_off;
                uint32_t alp = ahp + (uint32_t)ALO;
                uint32_t ah[4], al[4];
                ldm_x4(ah, ahp);
                ldm_x4(al, alp);
#pragma unroll
                for (int nt = 0; nt < 4; nt++) {
                    mma_bf16(acc[mt][nt], ah, bh[nt][0], bh[nt][1]);
                    mma_bf16(acc[mt][nt], ah, bl[nt][0], bl[nt][1]);
                    mma_bf16(acc[mt][nt], al, bh[nt][0], bh[nt][1]);
                }
            }
        }
    }

    // ---- epilogue ----
#pragma unroll
    for (int nt = 0; nt < 4; nt++) {
        int col = wc * 32 + nt * 8 + (lane & 3) * 2;
        float bias0 = 0.f, bias1 = 0.f;
        if (LAYER == 1) {
            bias0 = __ldg(b1 + col);
            bias1 = __ldg(b1 + col + 1);
        } else if (LAYER == 2 && col >= 64) {
            bias0 = __ldg(b2 + col - 64);
            bias1 = __ldg(b2 + col - 63);
        }
#pragma unroll
        for (int mt = 0; mt < 4; mt++) {
            int row0 = mbase + wr * 64 + mt * 16 + (lane >> 2);
#pragma unroll
            for (int hrow = 0; hrow < 2; hrow++) {
                int row = row0 + hrow * 8;
                if (row < NN) {
                    float v0 = acc[mt][nt][hrow * 2];
                    float v1 = acc[mt][nt][hrow * 2 + 1];
                    if (LAYER == 0) {
                        *(float2*)(g_xr + (size_t)row * 128 + col) = make_float2(v0, v1);
                    } else if (LAYER == 1) {
                        float2 xr = *(const float2*)(g_xr + (size_t)row * 128 + col);
                        v0 = fmaxf(v0 + xr.x + bias0, 0.f);
                        v1 = fmaxf(v1 + xr.y + bias1, 0.f);
                        uint32_t hi, lo;
                        split_pack(v0, v1, hi, lo);
                        g_hhi[(size_t)row * 64 + (col >> 1)] = hi;
                        g_hlo[(size_t)row * 64 + (col >> 1)] = lo;
                    } else {
                        *(float2*)(g_mean + (size_t)row * 128 + col) =
                            make_float2(v0 + bias0, v1 + bias1);
                    }
                }
            }
        }
    }
}

// ======================= final: log_softmax(mean_agg(p) + q) =======================
__global__ void k_final(float* __restrict__ out) {
    int node = blockIdx.x * (blockDim.x >> 5) + (threadIdx.x >> 5);
    if (node >= NN) return;
    int lane = threadIdx.x & 31;
    int b = g_rowptr[node], e = g_rowptr[node + 1];
    float2 acc = make_float2(0.f, 0.f);
    const float* PQ = g_mean;
    int i = b;
    for (; i + 4 <= e; i += 4) {
        int u0 = g_col[i + 0], u1 = g_col[i + 1], u2 = g_col[i + 2], u3 = g_col[i + 3];
        float2 v0 = *((const float2*)(PQ + (size_t)u0 * 128) + lane);
        float2 v1 = *((const float2*)(PQ + (size_t)u1 * 128) + lane);
        float2 v2 = *((const float2*)(PQ + (size_t)u2 * 128) + lane);
        float2 v3 = *((const float2*)(PQ + (size_t)u3 * 128) + lane);
        acc.x += (v0.x + v1.x) + (v2.x + v3.x);
        acc.y += (v0.y + v1.y) + (v2.y + v3.y);
    }
    for (; i < e; i++) {
        int u = g_col[i];
        float2 v = *((const float2*)(PQ + (size_t)u * 128) + lane);
        acc.x += v.x; acc.y += v.y;
    }
    float inv = 1.f / (float)max(e - b, 1);
    float2 q = *((const float2*)(PQ + (size_t)node * 128 + 64) + lane);
    float r0 = acc.x * inv + q.x;
    float r1 = acc.y * inv + q.y;

    float mx = fmaxf(r0, r1);
#pragma unroll
    for (int off = 16; off > 0; off >>= 1)
        mx = fmaxf(mx, __shfl_xor_sync(0xffffffffu, mx, off));
    float se = expf(r0 - mx) + expf(r1 - mx);
#pragma unroll
    for (int off = 16; off > 0; off >>= 1)
        se += __shfl_xor_sync(0xffffffffu, se, off);
    float l = logf(se);
    float2 o = make_float2(r0 - mx - l, r1 - mx - l);
    *((float2*)(out + (size_t)node * CC) + lane) = o;
}

// ======================= launch =======================
extern "C" void kernel_launch(void* const* d_in, const int* in_sizes, int n_in,
                              void* d_out, int out_size) {
    const float* x   = (const float*)d_in[0];
    const int*   ei  = (const int*)d_in[1];
    const int*   src = ei;
    const int*   dst = ei + NE;
    const float* W1l = (const float*)d_in[2];
    const float* b1l = (const float*)d_in[3];
    const float* W1r = (const float*)d_in[4];
    const float* W2l = (const float*)d_in[5];
    const float* b2l = (const float*)d_in[6];
    const float* W2r = (const float*)d_in[7];
    float* out = (float*)d_out;

    const int SMEM = 106496;
    static cudaStream_t s2 = nullptr;
    static cudaEvent_t evF = nullptr, evJ = nullptr;
    if (!s2) {
        cudaStreamCreateWithFlags(&s2, cudaStreamNonBlocking);
        cudaEventCreateWithFlags(&evF, cudaEventDisableTiming);
        cudaEventCreateWithFlags(&evJ, cudaEventDisableTiming);
        cudaFuncSetAttribute(k_mmagemm<0>, cudaFuncAttributeMaxDynamicSharedMemorySize, SMEM);
        cudaFuncSetAttribute(k_mmagemm<1>, cudaFuncAttributeMaxDynamicSharedMemorySize, SMEM);
        cudaFuncSetAttribute(k_mmagemm<2>, cudaFuncAttributeMaxDynamicSharedMemorySize, SMEM);
    }

    const int NB = (NN + 127) / 128;

    // ---- fork: side stream computes prepW + xr = x @ W1r^T ----
    cudaEventRecord(evF, 0);
    cudaStreamWaitEvent(s2, evF, 0);
    k_prepW<<<(128 * 256 + 128 * 128 + 255) / 256, 256, 0, s2>>>(W1l, W1r, W2l, W2r);
    k_mmagemm<0><<<NB, 256, SMEM, s2>>>(x, b1l, b2l);
    cudaEventRecord(evJ, s2);

    // ---- main chain: CSR build + aggregation (L2/atomic work, tensor idle) ----
    k_zero_cnt<<<(NN + 255) / 256, 256>>>();
    k_count<<<(NE + 255) / 256, 256>>>(dst);
    k_scan1<<<SCAN_NB, SCAN_B>>>();
    k_scan2<<<1, 128>>>();
    k_scan3<<<SCAN_NB, SCAN_B>>>();
    k_fill<<<(NE + 255) / 256, 256>>>(src, dst);
    k_agg128<<<(NN + 7) / 8, 256>>>(x);                  // g_mhi/g_mlo = mean(x) splits

    // ---- join, then the dependent GEMMs + final ----
    cudaStreamWaitEvent(0, evJ, 0);
    k_mmagemm<1><<<NB, 256, SMEM>>>(x, b1l, b2l);        // h -> g_hhi/g_hlo
    k_mmagemm<2><<<NB, 256, SMEM>>>(x, b1l, b2l);        // g_mean = [p | q]
    k_final<<<(NN + 7) / 8, 256>>>(out);
}

// round 7
// speedup vs baseline: 1.9095x; 1.0293x over previous
#include <cuda_runtime.h>
#include <cuda_bf16.h>
#include <cstdint>

#define NN 100000
#define NE 1600000
#define FF 128
#define CC 64
#define SCAN_B 1024
#define SCAN_NB ((NN + SCAN_B - 1) / SCAN_B)   // 98

// pipeline chunking (node ranges)
#define C0N 50048
#define C0B 391
#define C1N (NN - C0N)          // 49952
#define C1B ((C1N + 127) / 128) // 391

// ======================= scratch (static device globals) =======================
__device__ int   g_cnt[NN];
__device__ int   g_rowptr[NN + 1];
__device__ int   g_cursor[NN];
__device__ int   g_blksum[SCAN_NB];
__device__ int   g_col[NE];
__device__ uint32_t g_pbf[(size_t)NN * 32];    // P = h@W2l^T as packed bf16x2 (64 cols)
__device__ float g_q[(size_t)NN * 64];         // Q = h@W2r^T + b2l (fp32)
__device__ float g_xr[(size_t)NN * 128];       // x @ W1r^T (computed on side stream)
__device__ uint32_t g_mhi[(size_t)NN * 64];    // mean(x) packed bf16x2 hi
__device__ uint32_t g_mlo[(size_t)NN * 64];    // mean(x) packed bf16x2 lo
__device__ uint32_t g_hhi[(size_t)NN * 64];    // h packed bf16x2 hi
__device__ uint32_t g_hlo[(size_t)NN * 64];    // h packed bf16x2 lo
// weights as bf16 hi/lo, row-major [n][k]
__device__ unsigned short g_w1hi[128 * 256];
__device__ unsigned short g_w1lo[128 * 256];
__device__ unsigned short g_w2hi[128 * 128];
__device__ unsigned short g_w2lo[128 * 128];

// ======================= small helpers =======================
__device__ __forceinline__ uint32_t smem_to_u32(const void* p) {
    uint32_t a;
    asm("{ .reg .u64 t; cvta.to.shared.u64 t, %1; cvt.u32.u64 %0, t; }" : "=r"(a) : "l"(p));
    return a;
}

__device__ __forceinline__ void ldm_x4(uint32_t* r, uint32_t addr) {
    asm volatile("ldmatrix.sync.aligned.m8n8.x4.shared.b16 {%0,%1,%2,%3}, [%4];"
                 : "=r"(r[0]), "=r"(r[1]), "=r"(r[2]), "=r"(r[3]) : "r"(addr));
}

__device__ __forceinline__ void mma_bf16(float* d, const uint32_t* a, uint32_t b0, uint32_t b1) {
    asm volatile(
        "mma.sync.aligned.m16n8k16.row.col.f32.bf16.bf16.f32 "
        "{%0,%1,%2,%3}, {%4,%5,%6,%7}, {%8,%9}, {%0,%1,%2,%3};"
        : "+f"(d[0]), "+f"(d[1]), "+f"(d[2]), "+f"(d[3])
        : "r"(a[0]), "r"(a[1]), "r"(a[2]), "r"(a[3]), "r"(b0), "r"(b1));
}

__device__ __forceinline__ void split_pack(float a, float b, uint32_t& hi, uint32_t& lo) {
    __nv_bfloat16 ah = __float2bfloat16(a), bh = __float2bfloat16(b);
    float ar = a - __bfloat162float(ah);
    float br = b - __bfloat162float(bh);
    hi = (uint32_t)__bfloat16_as_ushort(ah) | ((uint32_t)__bfloat16_as_ushort(bh) << 16);
    lo = (uint32_t)__bfloat16_as_ushort(__float2bfloat16(ar))
       | ((uint32_t)__bfloat16_as_ushort(__float2bfloat16(br)) << 16);
}

__device__ __forceinline__ uint32_t pack_bf16x2(float a, float b) {
    return (uint32_t)__bfloat16_as_ushort(__float2bfloat16(a))
         | ((uint32_t)__bfloat16_as_ushort(__float2bfloat16(b)) << 16);
}

// ======================= CSR build =======================
__global__ void k_count(const int* __restrict__ dst) {
    int e = blockIdx.x * blockDim.x + threadIdx.x;
    if (e < NE) atomicAdd(&g_cnt[dst[e]], 1);
}

// per-block exclusive scan; also re-zeroes g_cnt for next graph replay
__global__ void k_scan1() {
    __shared__ int sh[SCAN_B];
    int t = threadIdx.x;
    int i = blockIdx.x * SCAN_B + t;
    int v = (i < NN) ? g_cnt[i] : 0;
    if (i < NN) g_cnt[i] = 0;
    sh[t] = v;
    __syncthreads();
#pragma unroll
    for (int off = 1; off < SCAN_B; off <<= 1) {
        int u = (t >= off) ? sh[t - off] : 0;
        __syncthreads();
        sh[t] += u;
        __syncthreads();
    }
    if (i < NN) g_rowptr[i] = sh[t] - v;
    if (t == SCAN_B - 1) g_blksum[blockIdx.x] = sh[t];
}

__global__ void k_scan2() {
    __shared__ int sh[128];
    int t = threadIdx.x;
    int v = (t < SCAN_NB) ? g_blksum[t] : 0;
    sh[t] = v;
    __syncthreads();
#pragma unroll
    for (int off = 1; off < 128; off <<= 1) {
        int u = (t >= off) ? sh[t - off] : 0;
        __syncthreads();
        sh[t] += u;
        __syncthreads();
    }
    if (t < SCAN_NB) g_blksum[t] = sh[t] - v;
}

__global__ void k_scan3() {
    int i = blockIdx.x * SCAN_B + threadIdx.x;
    if (i < NN) {
        int r = g_rowptr[i] + g_blksum[blockIdx.x];
        g_rowptr[i] = r;
        g_cursor[i] = r;
    }
    if (i == 0) g_rowptr[NN] = NE;
}

__global__ void k_fill(const int* __restrict__ src, const int* __restrict__ dst) {
    int e = blockIdx.x * blockDim.x + threadIdx.x;
    if (e < NE) {
        int d = dst[e];
        int pos = atomicAdd(&g_cursor[d], 1);
        g_col[pos] = src[e];
    }
}

// ======================= aggregation (warp per node) -> bf16 splits =======================
__global__ void k_agg128(const float* __restrict__ X, int nodeBase, int nodeCount) {
    int n = blockIdx.x * (blockDim.x >> 5) + (threadIdx.x >> 5);
    if (n >= nodeCount) return;
    int node = nodeBase + n;
    int lane = threadIdx.x & 31;
    int b = g_rowptr[node], e = g_rowptr[node + 1];
    float4 acc = make_float4(0.f, 0.f, 0.f, 0.f);
    int i = b;
    for (; i + 4 <= e; i += 4) {
        int u0 = g_col[i + 0], u1 = g_col[i + 1], u2 = g_col[i + 2], u3 = g_col[i + 3];
        float4 v0 = *((const float4*)(X + (size_t)u0 * FF) + lane);
        float4 v1 = *((const float4*)(X + (size_t)u1 * FF) + lane);
        float4 v2 = *((const float4*)(X + (size_t)u2 * FF) + lane);
        float4 v3 = *((const float4*)(X + (size_t)u3 * FF) + lane);
        acc.x += (v0.x + v1.x) + (v2.x + v3.x);
        acc.y += (v0.y + v1.y) + (v2.y + v3.y);
        acc.z += (v0.z + v1.z) + (v2.z + v3.z);
        acc.w += (v0.w + v1.w) + (v2.w + v3.w);
    }
    for (; i < e; i++) {
        int u = g_col[i];
        float4 v = *((const float4*)(X + (size_t)u * FF) + lane);
        acc.x += v.x; acc.y += v.y; acc.z += v.z; acc.w += v.w;
    }
    float inv = 1.f / (float)max(e - b, 1);
    uint32_t h0, l0, h1, l1;
    split_pack(acc.x * inv, acc.y * inv, h0, l0);
    split_pack(acc.z * inv, acc.w * inv, h1, l1);
    uint32_t* dh = g_mhi + (size_t)node * 64 + lane * 2;
    uint32_t* dl = g_mlo + (size_t)node * 64 + lane * 2;
    dh[0] = h0; dh[1] = h1;
    dl[0] = l0; dl[1] = l1;
}

// ======================= weight prep =======================
__global__ void k_prepW(const float* __restrict__ W1l, const float* __restrict__ W1r,
                        const float* __restrict__ W2l, const float* __restrict__ W2r) {
    int idx = blockIdx.x * blockDim.x + threadIdx.x;
    if (idx < 128 * 256) {
        int n = idx >> 8, k = idx & 255;
        float w = (k < 128) ? W1l[n * 128 + k] : W1r[n * 128 + (k - 128)];
        __nv_bfloat16 h = __float2bfloat16(w);
        g_w1hi[idx] = __bfloat16_as_ushort(h);
        g_w1lo[idx] = __bfloat16_as_ushort(__float2bfloat16(w - __bfloat162float(h)));
    } else {
        int i2 = idx - 128 * 256;
        if (i2 < 128 * 128) {
            int n = i2 >> 7, k = i2 & 127;
            float w = (n < 64) ? W2l[n * 128 + k] : W2r[(n - 64) * 128 + k];
            __nv_bfloat16 h = __float2bfloat16(w);
            g_w2hi[i2] = __bfloat16_as_ushort(h);
            g_w2lo[i2] = __bfloat16_as_ushort(__float2bfloat16(w - __bfloat162float(h)));
        }
    }
}

// ======================= HMMA GEMM (all K=128) =======================
// LAYER 0: xr = x @ W1r^T                   -> g_xr fp32   (side stream, full range)
// LAYER 1: h  = relu(mean @ W1l^T + xr +b1) -> g_hhi/g_hlo (chunked)
// LAYER 2: P|Q = h @ [W2l;W2r]^T (+b2 hi)   -> g_pbf bf16 / g_q fp32 (chunked)
#define ASTR 72
#define BSTR 136

template <int LAYER>
__global__ void __launch_bounds__(256, 2)
k_mmagemm(const float* __restrict__ X, const float* __restrict__ b1,
          const float* __restrict__ b2, int moff)
{
    constexpr int AHI   = 0;
    constexpr int ALO   = 128 * ASTR * 2;
    constexpr int BHI   = 2 * 128 * ASTR * 2;
    constexpr int BSPL  = 128 * BSTR * 2;
    constexpr int BLO   = BHI + BSPL;

    extern __shared__ char smem[];
    const uint32_t smem_base = smem_to_u32(smem);
    const int tid  = threadIdx.x;
    const int warp = tid >> 5;
    const int lane = tid & 31;
    const int wr   = warp >> 2;
    const int wc   = warp & 3;
    const int mbase = moff + blockIdx.x * 128;

    {
        const uint4* shi;
        const uint4* slo;
        int srowv, woff8;
        if (LAYER <= 1) {
            shi = (const uint4*)g_w1hi; slo = (const uint4*)g_w1lo;
            srowv = 32; woff8 = (LAYER == 0) ? 16 : 0;
        } else {
            shi = (const uint4*)g_w2hi; slo = (const uint4*)g_w2lo;
            srowv = 16; woff8 = 0;
        }
        for (int i = tid; i < 128 * 16; i += 256) {
            int n = i >> 4, c = i & 15;
            *(uint4*)(smem + BHI + n * (BSTR * 2) + c * 16) = shi[n * srowv + woff8 + c];
            *(uint4*)(smem + BLO + n * (BSTR * 2) + c * 16) = slo[n * srowv + woff8 + c];
        }
    }

    float acc[4][4][4];
#pragma unroll
    for (int mt = 0; mt < 4; mt++)
#pragma unroll
        for (int nt = 0; nt < 4; nt++)
#pragma unroll
            for (int q = 0; q < 4; q++) acc[mt][nt][q] = 0.f;

    const uint32_t a_lane_off = (uint32_t)(((lane & 15) * ASTR + (lane >> 4) * 8) * 2);
    const uint32_t* Bh = (const uint32_t*)(smem + BHI);
    const uint32_t* Bl = (const uint32_t*)(smem + BLO);

#pragma unroll
    for (int ch = 0; ch < 2; ch++) {
        __syncthreads();
        {
            int row  = tid >> 1;
            int half = tid & 1;
            int gr   = mbase + row;
            bool valid = gr < NN;
            uint32_t* dAh = (uint32_t*)(smem + AHI + row * (ASTR * 2));
            uint32_t* dAl = (uint32_t*)(smem + ALO + row * (ASTR * 2));
            if (LAYER == 0) {
                const float* src = X + (size_t)gr * 128 + ch * 64 + half * 32;
#pragma unroll
                for (int j = 0; j < 8; j++) {
                    float4 v = make_float4(0.f, 0.f, 0.f, 0.f);
                    if (valid) v = *(const float4*)(src + j * 4);
                    uint32_t h0, l0, h1, l1;
                    split_pack(v.x, v.y, h0, l0);
                    split_pack(v.z, v.w, h1, l1);
                    int o = half * 16 + j * 2;
                    dAh[o] = h0; dAh[o + 1] = h1;
                    dAl[o] = l0; dAl[o + 1] = l1;
                }
            } else {
                const uint32_t* shi = (LAYER == 1) ? g_mhi : g_hhi;
                const uint32_t* slo = (LAYER == 1) ? g_mlo : g_hlo;
                size_t off = (size_t)gr * 64 + ch * 32 + half * 16;
#pragma unroll
                for (int j = 0; j < 4; j++) {
                    uint4 vh = make_uint4(0u, 0u, 0u, 0u), vl = vh;
                    if (valid) {
                        vh = *(const uint4*)(shi + off + j * 4);
                        vl = *(const uint4*)(slo + off + j * 4);
                    }
                    *(uint4*)(dAh + half * 16 + j * 4) = vh;
                    *(uint4*)(dAl + half * 16 + j * 4) = vl;
                }
            }
        }
        __syncthreads();

#pragma unroll
        for (int ks = 0; ks < 4; ks++) {
            const int k0 = ks * 16;
            uint32_t bh[4][2], bl[4][2];
#pragma unroll
            for (int nt = 0; nt < 4; nt++) {
                int n = wc * 32 + nt * 8 + (lane >> 2);
                int bi = n * (BSTR / 2) + (ch * 64 + k0) / 2 + (lane & 3);
                bh[nt][0] = Bh[bi];     bh[nt][1] = Bh[bi + 4];
                bl[nt][0] = Bl[bi];     bl[nt][1] = Bl[bi + 4];
            }
#pragma unroll
            for (int mt = 0; mt < 4; mt++) {
                uint32_t ahp = smem_base + AHI + (uint32_t)((wr * 64 + mt * 16) * ASTR + k0) * 2 + a_lane_off;
                uint32_t alp = ahp + (uint32_t)ALO;
                uint32_t ah[4], al[4];
                ldm_x4(ah, ahp);
                ldm_x4(al, alp);
#pragma unroll
                for (int nt = 0; nt < 4; nt++) {
                    mma_bf16(acc[mt][nt], ah, bh[nt][0], bh[nt][1]);
                    mma_bf16(acc[mt][nt], ah, bl[nt][0], bl[nt][1]);
                    mma_bf16(acc[mt][nt], al, bh[nt][0], bh[nt][1]);
                }
            }
        }
    }

    // ---- epilogue ----
#pragma unroll
    for (int nt = 0; nt < 4; nt++) {
        int col = wc * 32 + nt * 8 + (lane & 3) * 2;
        float bias0 = 0.f, bias1 = 0.f;
        if (LAYER == 1) {
            bias0 = __ldg(b1 + col);
            bias1 = __ldg(b1 + col + 1);
        } else if (LAYER == 2 && col >= 64) {
            bias0 = __ldg(b2 + col - 64);
            bias1 = __ldg(b2 + col - 63);
        }
#pragma unroll
        for (int mt = 0; mt < 4; mt++) {
            int row0 = mbase + wr * 64 + mt * 16 + (lane >> 2);
#pragma unroll
            for (int hrow = 0; hrow < 2; hrow++) {
                int row = row0 + hrow * 8;
                if (row < NN) {
                    float v0 = acc[mt][nt][hrow * 2];
                    float v1 = acc[mt][nt][hrow * 2 + 1];
                    if (LAYER == 0) {
                        *(float2*)(g_xr + (size_t)row * 128 + col) = make_float2(v0, v1);
                    } else if (LAYER == 1) {
                        float2 xr = *(const float2*)(g_xr + (size_t)row * 128 + col);
                        v0 = fmaxf(v0 + xr.x + bias0, 0.f);
                        v1 = fmaxf(v1 + xr.y + bias1, 0.f);
                        uint32_t hi, lo;
                        split_pack(v0, v1, hi, lo);
                        g_hhi[(size_t)row * 64 + (col >> 1)] = hi;
                        g_hlo[(size_t)row * 64 + (col >> 1)] = lo;
                    } else {
                        if (col < 64) {
                            g_pbf[(size_t)row * 32 + (col >> 1)] = pack_bf16x2(v0, v1);
                        } else {
                            *(float2*)(g_q + (size_t)row * 64 + (col - 64)) =
                                make_float2(v0 + bias0, v1 + bias1);
                        }
                    }
                }
            }
        }
    }
}

// ======================= final: log_softmax(mean_agg(P) + Q) =======================
__global__ void k_final(float* __restrict__ out) {
    int node = blockIdx.x * (blockDim.x >> 5) + (threadIdx.x >> 5);
    if (node >= NN) return;
    int lane = threadIdx.x & 31;
    int b = g_rowptr[node], e = g_rowptr[node + 1];
    float a0 = 0.f, a1 = 0.f;
    int i = b;
    for (; i + 4 <= e; i += 4) {
        int u0 = g_col[i + 0], u1 = g_col[i + 1], u2 = g_col[i + 2], u3 = g_col[i + 3];
        uint32_t w0 = g_pbf[(size_t)u0 * 32 + lane];
        uint32_t w1 = g_pbf[(size_t)u1 * 32 + lane];
        uint32_t w2 = g_pbf[(size_t)u2 * 32 + lane];
        uint32_t w3 = g_pbf[(size_t)u3 * 32 + lane];
        a0 += __uint_as_float(w0 << 16) + __uint_as_float(w1 << 16)
            + __uint_as_float(w2 << 16) + __uint_as_float(w3 << 16);
        a1 += __uint_as_float(w0 & 0xffff0000u) + __uint_as_float(w1 & 0xffff0000u)
            + __uint_as_float(w2 & 0xffff0000u) + __uint_as_float(w3 & 0xffff0000u);
    }
    for (; i < e; i++) {
        uint32_t w = g_pbf[(size_t)g_col[i] * 32 + lane];
        a0 += __uint_as_float(w << 16);
        a1 += __uint_as_float(w & 0xffff0000u);
    }
    float inv = 1.f / (float)max(e - b, 1);
    float2 q = *((const float2*)(g_q + (size_t)node * 64) + lane);
    float r0 = a0 * inv + q.x;
    float r1 = a1 * inv + q.y;

    float mx = fmaxf(r0, r1);
#pragma unroll
    for (int off = 16; off > 0; off >>= 1)
        mx = fmaxf(mx, __shfl_xor_sync(0xffffffffu, mx, off));
    float se = expf(r0 - mx) + expf(r1 - mx);
#pragma unroll
    for (int off = 16; off > 0; off >>= 1)
        se += __shfl_xor_sync(0xffffffffu, se, off);
    float l = logf(se);
    float2 o = make_float2(r0 - mx - l, r1 - mx - l);
    *((float2*)(out + (size_t)node * CC) + lane) = o;
}

// ======================= launch =======================
extern "C" void kernel_launch(void* const* d_in, const int* in_sizes, int n_in,
                              void* d_out, int out_size) {
    const float* x   = (const float*)d_in[0];
    const int*   ei  = (const int*)d_in[1];
    const int*   src = ei;
    const int*   dst = ei + NE;
    const float* W1l = (const float*)d_in[2];
    const float* b1l = (const float*)d_in[3];
    const float* W1r = (const float*)d_in[4];
    const float* W2l = (const float*)d_in[5];
    const float* b2l = (const float*)d_in[6];
    const float* W2r = (const float*)d_in[7];
    float* out = (float*)d_out;

    const int SMEM = 106496;
    static cudaStream_t s2 = nullptr, s3 = nullptr;
    static cudaEvent_t evF = nullptr, evJ = nullptr, evFill = nullptr, evB = nullptr;
    if (!s2) {
        cudaStreamCreateWithFlags(&s2, cudaStreamNonBlocking);
        cudaStreamCreateWithFlags(&s3, cudaStreamNonBlocking);
        cudaEventCreateWithFlags(&evF, cudaEventDisableTiming);
        cudaEventCreateWithFlags(&evJ, cudaEventDisableTiming);
        cudaEventCreateWithFlags(&evFill, cudaEventDisableTiming);
        cudaEventCreateWithFlags(&evB, cudaEventDisableTiming);
        cudaFuncSetAttribute(k_mmagemm<0>, cudaFuncAttributeMaxDynamicSharedMemorySize, SMEM);
        cudaFuncSetAttribute(k_mmagemm<1>, cudaFuncAttributeMaxDynamicSharedMemorySize, SMEM);
        cudaFuncSetAttribute(k_mmagemm<2>, cudaFuncAttributeMaxDynamicSharedMemorySize, SMEM);
    }

    // ---- fork: side stream computes prepW + xr = x @ W1r^T (full range) ----
    cudaEventRecord(evF, 0);
    cudaStreamWaitEvent(s2, evF, 0);
    k_prepW<<<(128 * 256 + 128 * 128 + 255) / 256, 256, 0, s2>>>(W1l, W1r, W2l, W2r);
    k_mmagemm<0><<<(NN + 127) / 128, 256, SMEM, s2>>>(x, b1l, b2l, 0);
    cudaEventRecord(evJ, s2);

    // ---- main chain: CSR build ----
    k_count<<<(NE + 255) / 256, 256>>>(dst);
    k_scan1<<<SCAN_NB, SCAN_B>>>();
    k_scan2<<<1, 128>>>();
    k_scan3<<<SCAN_NB, SCAN_B>>>();
    k_fill<<<(NE + 255) / 256, 256>>>(src, dst);
    cudaEventRecord(evFill, 0);

    // ---- chunk 1 on s3: agg1 -> gemm1_1 -> gemm2_1 ----
    cudaStreamWaitEvent(s3, evFill, 0);
    k_agg128<<<(C1N + 7) / 8, 256, 0, s3>>>(x, C0N, C1N);
    cudaStreamWaitEvent(s3, evJ, 0);
    k_mmagemm<1><<<C1B, 256, SMEM, s3>>>(x, b1l, b2l, C0N);
    k_mmagemm<2><<<C1B, 256, SMEM, s3>>>(x, b1l, b2l, C0N);
    cudaEventRecord(evB, s3);

    // ---- chunk 0 on main: agg0 -> gemm1_0 -> gemm2_0 ----
    k_agg128<<<(C0N + 7) / 8, 256>>>(x, 0, C0N);
    cudaStreamWaitEvent(0, evJ, 0);
    k_mmagemm<1><<<C0B, 256, SMEM>>>(x, b1l, b2l, 0);
    k_mmagemm<2><<<C0B, 256, SMEM>>>(x, b1l, b2l, 0);

    // ---- join chunk 1, then final ----
    cudaStreamWaitEvent(0, evB, 0);
    k_final<<<(NN + 7) / 8, 256>>>(out);
}